// round 1
// baseline (speedup 1.0000x reference)
#include <cuda_runtime.h>

#define TT 128
#define BSZ 128
#define NV 32
#define SD 64

// Gain matrices K_t, t = 0..126, layout K[(t*64 + s)*32 + v]
__device__ float g_K[(TT - 1) * SD * NV];

// ---------------------------------------------------------------------------
// Phase 1: single CTA, 256 threads. Computes the batch-independent K_t chain.
// Covariance recursion entirely in shared memory (fp32, padded leading dims).
// ---------------------------------------------------------------------------
__global__ __launch_bounds__(256, 1) void kf_phase1(
    const float* __restrict__ Fm, const float* __restrict__ Hm,
    const float* __restrict__ Rm, const float* __restrict__ Qm)
{
    extern __shared__ float sm[];
    float* sF   = sm;                 // [64][65]
    float* sH   = sF  + 64 * 65;      // [32][65]
    float* sR   = sH  + 32 * 65;      // [32][33]
    float* sQ   = sR  + 32 * 33;      // [64][65]
    float* P    = sQ  + 64 * 65;      // [64][65]
    float* T1   = P   + 64 * 65;      // [64][65]
    float* T2   = T1  + 64 * 65;      // [64][65]
    float* PHt  = T2  + 64 * 65;      // [64][33]
    float* aug  = PHt + 64 * 33;      // [32][97]  (S | PHt^T)
    float* fac  = aug + 32 * 97;      // [32]
    float* dinv = fac + 32;           // [32]
    float* spinv= dinv + 32;          // [1]

    const int tid = threadIdx.x;

    // Load constants, init P = I
    for (int idx = tid; idx < 64 * 64; idx += 256) {
        int i = idx >> 6, j = idx & 63;
        sF[i * 65 + j] = Fm[idx];
        sQ[i * 65 + j] = Qm[idx];
        P [i * 65 + j] = (i == j) ? 1.0f : 0.0f;
    }
    for (int idx = tid; idx < 32 * 64; idx += 256) {
        int i = idx >> 6, j = idx & 63;
        sH[i * 65 + j] = Hm[idx];
    }
    for (int idx = tid; idx < 32 * 32; idx += 256) {
        int i = idx >> 5, j = idx & 31;
        sR[i * 33 + j] = Rm[idx];
    }
    __syncthreads();

    const int ty = tid >> 4;   // 0..15
    const int tx = tid & 15;   // 0..15

    for (int t = 0; t < TT - 1; ++t) {
        // ---- PHt[64][32] = P @ H^T ----
        {
            int i0 = ty * 4, v0 = tx * 2;
            float a00 = 0, a01 = 0, a10 = 0, a11 = 0;
            float a20 = 0, a21 = 0, a30 = 0, a31 = 0;
            #pragma unroll 8
            for (int k = 0; k < 64; ++k) {
                float b0 = sH[(v0    ) * 65 + k];
                float b1 = sH[(v0 + 1) * 65 + k];
                float p0 = P[(i0    ) * 65 + k];
                float p1 = P[(i0 + 1) * 65 + k];
                float p2 = P[(i0 + 2) * 65 + k];
                float p3 = P[(i0 + 3) * 65 + k];
                a00 += p0 * b0; a01 += p0 * b1;
                a10 += p1 * b0; a11 += p1 * b1;
                a20 += p2 * b0; a21 += p2 * b1;
                a30 += p3 * b0; a31 += p3 * b1;
            }
            PHt[(i0    ) * 33 + v0] = a00; PHt[(i0    ) * 33 + v0 + 1] = a01;
            PHt[(i0 + 1) * 33 + v0] = a10; PHt[(i0 + 1) * 33 + v0 + 1] = a11;
            PHt[(i0 + 2) * 33 + v0] = a20; PHt[(i0 + 2) * 33 + v0 + 1] = a21;
            PHt[(i0 + 3) * 33 + v0] = a30; PHt[(i0 + 3) * 33 + v0 + 1] = a31;
        }
        __syncthreads();

        // ---- aug left  = S = H @ PHt + R   [32][32]
        //      aug right = PHt^T             [32][64]
        {
            int i  = tid >> 3;        // 0..31
            int j0 = (tid & 7) * 4;   // 0..28
            float c0 = 0, c1 = 0, c2 = 0, c3 = 0;
            #pragma unroll 8
            for (int k = 0; k < 64; ++k) {
                float a = sH[i * 65 + k];
                const float* bp = &PHt[k * 33 + j0];
                c0 += a * bp[0]; c1 += a * bp[1];
                c2 += a * bp[2]; c3 += a * bp[3];
            }
            aug[i * 97 + j0    ] = c0 + sR[i * 33 + j0    ];
            aug[i * 97 + j0 + 1] = c1 + sR[i * 33 + j0 + 1];
            aug[i * 97 + j0 + 2] = c2 + sR[i * 33 + j0 + 2];
            aug[i * 97 + j0 + 3] = c3 + sR[i * 33 + j0 + 3];
        }
        for (int idx = tid; idx < 32 * 64; idx += 256) {
            int i = idx >> 6, j = idx & 63;
            aug[i * 97 + 32 + j] = PHt[j * 33 + i];
        }
        __syncthreads();

        // ---- Gauss-Jordan (no pivoting, S is SPD): left part -> diagonal ----
        {
            const int r  = tid >> 3;   // 0..31
            const int jb = tid & 7;
            for (int piv = 0; piv < 32; ++piv) {
                if (tid < 32) fac[tid] = aug[tid * 97 + piv];
                if (tid == 0) spinv[0] = 1.0f / aug[piv * 97 + piv];
                __syncthreads();
                float f = fac[r] * spinv[0];
                if (r != piv) {
                    const float* pr = &aug[piv * 97];
                    float* rr = &aug[r * 97];
                    for (int j = jb; j < 97; j += 8)
                        rr[j] -= f * pr[j];
                }
                __syncthreads();
            }
            if (tid < 32) dinv[tid] = 1.0f / aug[tid * 97 + tid];
            __syncthreads();
        }

        // ---- K_t = (D^-1 * aug_right)^T  -> global ----
        for (int idx = tid; idx < SD * NV; idx += 256) {
            int s = idx >> 5, v = idx & 31;
            g_K[t * (SD * NV) + idx] = aug[v * 97 + 32 + s] * dinv[v];
        }
        if (t == TT - 2) break;   // last gain computed; P no longer needed

        // fold D^-1 into PHt so T1 = P - PHt @ aug_right
        for (int idx = tid; idx < 64 * 32; idx += 256) {
            int i = idx >> 5, v = idx & 31;
            PHt[i * 33 + v] *= dinv[v];
        }
        __syncthreads();

        // ---- T1 = P - PHt @ aug_right   [64][64], K = 32 ----
        {
            int i0 = ty * 4, j0 = tx * 4;
            float acc[4][4];
            #pragma unroll
            for (int r = 0; r < 4; ++r)
                #pragma unroll
                for (int c = 0; c < 4; ++c)
                    acc[r][c] = P[(i0 + r) * 65 + j0 + c];
            #pragma unroll 4
            for (int v = 0; v < 32; ++v) {
                float a0 = PHt[(i0    ) * 33 + v];
                float a1 = PHt[(i0 + 1) * 33 + v];
                float a2 = PHt[(i0 + 2) * 33 + v];
                float a3 = PHt[(i0 + 3) * 33 + v];
                const float* bp = &aug[v * 97 + 32 + j0];
                float b0 = bp[0], b1 = bp[1], b2 = bp[2], b3 = bp[3];
                acc[0][0] -= a0 * b0; acc[0][1] -= a0 * b1; acc[0][2] -= a0 * b2; acc[0][3] -= a0 * b3;
                acc[1][0] -= a1 * b0; acc[1][1] -= a1 * b1; acc[1][2] -= a1 * b2; acc[1][3] -= a1 * b3;
                acc[2][0] -= a2 * b0; acc[2][1] -= a2 * b1; acc[2][2] -= a2 * b2; acc[2][3] -= a2 * b3;
                acc[3][0] -= a3 * b0; acc[3][1] -= a3 * b1; acc[3][2] -= a3 * b2; acc[3][3] -= a3 * b3;
            }
            #pragma unroll
            for (int r = 0; r < 4; ++r)
                #pragma unroll
                for (int c = 0; c < 4; ++c)
                    T1[(i0 + r) * 65 + j0 + c] = acc[r][c];
        }
        __syncthreads();

        // ---- T2 = F @ T1   [64][64] ----
        {
            int i0 = ty * 4, j0 = tx * 4;
            float acc[4][4] = {};
            #pragma unroll 4
            for (int k = 0; k < 64; ++k) {
                float a0 = sF[(i0    ) * 65 + k];
                float a1 = sF[(i0 + 1) * 65 + k];
                float a2 = sF[(i0 + 2) * 65 + k];
                float a3 = sF[(i0 + 3) * 65 + k];
                const float* bp = &T1[k * 65 + j0];
                float b0 = bp[0], b1 = bp[1], b2 = bp[2], b3 = bp[3];
                acc[0][0] += a0 * b0; acc[0][1] += a0 * b1; acc[0][2] += a0 * b2; acc[0][3] += a0 * b3;
                acc[1][0] += a1 * b0; acc[1][1] += a1 * b1; acc[1][2] += a1 * b2; acc[1][3] += a1 * b3;
                acc[2][0] += a2 * b0; acc[2][1] += a2 * b1; acc[2][2] += a2 * b2; acc[2][3] += a2 * b3;
                acc[3][0] += a3 * b0; acc[3][1] += a3 * b1; acc[3][2] += a3 * b2; acc[3][3] += a3 * b3;
            }
            #pragma unroll
            for (int r = 0; r < 4; ++r)
                #pragma unroll
                for (int c = 0; c < 4; ++c)
                    T2[(i0 + r) * 65 + j0 + c] = acc[r][c];
        }
        __syncthreads();

        // ---- P = T2 @ F^T + Q   [64][64] ----
        {
            int i0 = ty * 4, j0 = tx * 4;
            float acc[4][4];
            #pragma unroll
            for (int r = 0; r < 4; ++r)
                #pragma unroll
                for (int c = 0; c < 4; ++c)
                    acc[r][c] = sQ[(i0 + r) * 65 + j0 + c];
            #pragma unroll 4
            for (int k = 0; k < 64; ++k) {
                float a0 = T2[(i0    ) * 65 + k];
                float a1 = T2[(i0 + 1) * 65 + k];
                float a2 = T2[(i0 + 2) * 65 + k];
                float a3 = T2[(i0 + 3) * 65 + k];
                float b0 = sF[(j0    ) * 65 + k];
                float b1 = sF[(j0 + 1) * 65 + k];
                float b2 = sF[(j0 + 2) * 65 + k];
                float b3 = sF[(j0 + 3) * 65 + k];
                acc[0][0] += a0 * b0; acc[0][1] += a0 * b1; acc[0][2] += a0 * b2; acc[0][3] += a0 * b3;
                acc[1][0] += a1 * b0; acc[1][1] += a1 * b1; acc[1][2] += a1 * b2; acc[1][3] += a1 * b3;
                acc[2][0] += a2 * b0; acc[2][1] += a2 * b1; acc[2][2] += a2 * b2; acc[2][3] += a2 * b3;
                acc[3][0] += a3 * b0; acc[3][1] += a3 * b1; acc[3][2] += a3 * b2; acc[3][3] += a3 * b3;
            }
            #pragma unroll
            for (int r = 0; r < 4; ++r)
                #pragma unroll
                for (int c = 0; c < 4; ++c)
                    P[(i0 + r) * 65 + j0 + c] = acc[r][c];
        }
        __syncthreads();
    }
}

// ---------------------------------------------------------------------------
// Phase 2: one CTA per batch (128 CTAs, 64 threads). Mean recursion using the
// precomputed K_t. K row for the next step is prefetched into registers.
// ---------------------------------------------------------------------------
__global__ __launch_bounds__(64, 1) void kf_phase2(
    const float* __restrict__ x, const float* __restrict__ Fm,
    const float* __restrict__ Hm, float* __restrict__ out)
{
    __shared__ float sH[32 * 65];
    __shared__ float sF[64 * 65];
    __shared__ float sx[32 * 128];
    __shared__ float m[64];
    __shared__ float mu[64];
    __shared__ float resid[32];

    const int b = blockIdx.x;
    const int tid = threadIdx.x;

    for (int idx = tid; idx < 64 * 64; idx += 64) {
        int i = idx >> 6, j = idx & 63;
        sF[i * 65 + j] = Fm[idx];
    }
    for (int idx = tid; idx < 32 * 64; idx += 64) {
        int i = idx >> 6, j = idx & 63;
        sH[i * 65 + j] = Hm[idx];
    }
    for (int idx = tid; idx < 32 * 128; idx += 64)
        sx[idx] = x[b * (32 * 128) + idx];
    m[tid] = 0.0f;
    if (tid < 32) out[b * (32 * 128) + tid * 128 + 0] = 0.0f;   // t = 0 column
    __syncthreads();

    // prefetch K row (32 floats) for t = 0
    const float4* Kp = reinterpret_cast<const float4*>(g_K);
    float4 kreg[8];
    #pragma unroll
    for (int q = 0; q < 8; ++q) kreg[q] = Kp[(0 * 64 + tid) * 8 + q];

    for (int t = 0; t < TT - 1; ++t) {
        // resid = o_t - H @ m
        if (tid < 32) {
            const float* hr = &sH[tid * 65];
            float acc = 0.0f;
            #pragma unroll
            for (int k = 0; k < 64; ++k) acc += hr[k] * m[k];
            resid[tid] = sx[tid * 128 + t] - acc;
        }
        __syncthreads();

        // mu = m + K_t @ resid   (K row in registers); prefetch next K row
        {
            float acc = m[tid];
            #pragma unroll
            for (int q = 0; q < 8; ++q) {
                float4 kv = kreg[q];
                acc += kv.x * resid[q * 4 + 0] + kv.y * resid[q * 4 + 1]
                     + kv.z * resid[q * 4 + 2] + kv.w * resid[q * 4 + 3];
            }
            mu[tid] = acc;
            if (t + 1 < TT - 1) {
                #pragma unroll
                for (int q = 0; q < 8; ++q)
                    kreg[q] = Kp[((t + 1) * 64 + tid) * 8 + q];
            }
        }
        __syncthreads();

        // m = F @ mu
        {
            const float* fr = &sF[tid * 65];
            float acc = 0.0f;
            #pragma unroll
            for (int k = 0; k < 64; ++k) acc += fr[k] * mu[k];
            m[tid] = acc;
        }
        __syncthreads();

        // y = H @ m  -> out[:, :, t+1]
        if (tid < 32) {
            const float* hr = &sH[tid * 65];
            float acc = 0.0f;
            #pragma unroll
            for (int k = 0; k < 64; ++k) acc += hr[k] * m[k];
            out[b * (32 * 128) + tid * 128 + (t + 1)] = acc;
        }
        __syncthreads();
    }
}

extern "C" void kernel_launch(void* const* d_in, const int* in_sizes, int n_in,
                              void* d_out, int out_size)
{
    const float* x = (const float*)d_in[0];
    const float* F = (const float*)d_in[1];
    const float* H = (const float*)d_in[2];
    const float* R = (const float*)d_in[3];
    const float* Q = (const float*)d_in[4];
    float* out = (float*)d_out;

    const int smem1 = (64 * 65 * 5 + 32 * 65 + 32 * 33 + 64 * 33 + 32 * 97 + 65)
                      * (int)sizeof(float);
    cudaFuncSetAttribute(kf_phase1, cudaFuncAttributeMaxDynamicSharedMemorySize, smem1);

    kf_phase1<<<1, 256, smem1>>>(F, H, R, Q);
    kf_phase2<<<BSZ, 64>>>(x, F, H, out);
}

// round 3
// speedup vs baseline: 7.4614x; 7.4614x over previous
#include <cuda_runtime.h>

#define TT 128
#define BSZ 128
#define NV 32
#define SD 64

// Gain matrices K_t, t = 0..126, layout K[(t*64 + s)*32 + v]
__device__ float g_K[(TT - 1) * SD * NV];

// ---------------------------------------------------------------------------
// Phase 1: single CTA, 256 threads. Computes the batch-independent K_t chain.
// Exploits Riccati contraction: once K converges (fp32 noise floor), the
// remaining gains are identical — fill and exit.
// ---------------------------------------------------------------------------
__global__ __launch_bounds__(256, 1) void kf_phase1(
    const float* __restrict__ Fm, const float* __restrict__ Hm,
    const float* __restrict__ Rm, const float* __restrict__ Qm)
{
    extern __shared__ float sm[];
    float* sF   = sm;                 // [64][65]
    float* sH   = sF  + 64 * 65;      // [32][65]
    float* sR   = sH  + 32 * 65;      // [32][33]
    float* sQ   = sR  + 32 * 33;      // [64][65]
    float* P    = sQ  + 64 * 65;      // [64][65]
    float* T1   = P   + 64 * 65;      // [64][65]
    float* T2   = T1  + 64 * 65;      // [64][65]
    float* PHt  = T2  + 64 * 65;      // [64][33]
    float* aug  = PHt + 64 * 33;      // [32][97]  (S | PHt^T)
    float* dinv = aug + 32 * 97;      // [32]
    float* Kb   = dinv + 32;          // [64*32] previous K (for convergence)
    int*   red  = (int*)(Kb + 64 * 32); // [1] reduction slot

    const int tid = threadIdx.x;

    // Load constants, init P = I, Kb = big
    for (int idx = tid; idx < 64 * 64; idx += 256) {
        int i = idx >> 6, j = idx & 63;
        sF[i * 65 + j] = Fm[idx];
        sQ[i * 65 + j] = Qm[idx];
        P [i * 65 + j] = (i == j) ? 1.0f : 0.0f;
    }
    for (int idx = tid; idx < 32 * 64; idx += 256) {
        int i = idx >> 6, j = idx & 63;
        sH[i * 65 + j] = Hm[idx];
    }
    for (int idx = tid; idx < 32 * 32; idx += 256) {
        int i = idx >> 5, j = idx & 31;
        sR[i * 33 + j] = Rm[idx];
    }
    for (int idx = tid; idx < 64 * 32; idx += 256) Kb[idx] = 1e30f;
    __syncthreads();

    const int ty = tid >> 4;   // 0..15
    const int tx = tid & 15;   // 0..15

    for (int t = 0; t < TT - 1; ++t) {
        // ---- PHt[64][32] = P @ H^T ----
        {
            int i0 = ty * 4, v0 = tx * 2;
            float a00 = 0, a01 = 0, a10 = 0, a11 = 0;
            float a20 = 0, a21 = 0, a30 = 0, a31 = 0;
            #pragma unroll 8
            for (int k = 0; k < 64; ++k) {
                float b0 = sH[(v0    ) * 65 + k];
                float b1 = sH[(v0 + 1) * 65 + k];
                float p0 = P[(i0    ) * 65 + k];
                float p1 = P[(i0 + 1) * 65 + k];
                float p2 = P[(i0 + 2) * 65 + k];
                float p3 = P[(i0 + 3) * 65 + k];
                a00 += p0 * b0; a01 += p0 * b1;
                a10 += p1 * b0; a11 += p1 * b1;
                a20 += p2 * b0; a21 += p2 * b1;
                a30 += p3 * b0; a31 += p3 * b1;
            }
            PHt[(i0    ) * 33 + v0] = a00; PHt[(i0    ) * 33 + v0 + 1] = a01;
            PHt[(i0 + 1) * 33 + v0] = a10; PHt[(i0 + 1) * 33 + v0 + 1] = a11;
            PHt[(i0 + 2) * 33 + v0] = a20; PHt[(i0 + 2) * 33 + v0 + 1] = a21;
            PHt[(i0 + 3) * 33 + v0] = a30; PHt[(i0 + 3) * 33 + v0 + 1] = a31;
        }
        __syncthreads();

        // ---- aug left = S = H @ PHt + R ; aug right = PHt^T ----
        {
            int i  = tid >> 3;
            int j0 = (tid & 7) * 4;
            float c0 = 0, c1 = 0, c2 = 0, c3 = 0;
            #pragma unroll 8
            for (int k = 0; k < 64; ++k) {
                float a = sH[i * 65 + k];
                const float* bp = &PHt[k * 33 + j0];
                c0 += a * bp[0]; c1 += a * bp[1];
                c2 += a * bp[2]; c3 += a * bp[3];
            }
            aug[i * 97 + j0    ] = c0 + sR[i * 33 + j0    ];
            aug[i * 97 + j0 + 1] = c1 + sR[i * 33 + j0 + 1];
            aug[i * 97 + j0 + 2] = c2 + sR[i * 33 + j0 + 2];
            aug[i * 97 + j0 + 3] = c3 + sR[i * 33 + j0 + 3];
        }
        for (int idx = tid; idx < 32 * 64; idx += 256) {
            int i = idx >> 6, j = idx & 63;
            aug[i * 97 + 32 + j] = PHt[j * 33 + i];
        }
        __syncthreads();

        // ---- Gauss-Jordan, ONE barrier per pivot ----
        // Each row's 8 threads live in one warp: reads of the factor column
        // complete before in-warp writes via __syncwarp. Pivot row is never
        // written during its own elimination.
        {
            const int r  = tid >> 3;
            const int jb = tid & 7;
            float* rr = &aug[r * 97];
            for (int piv = 0; piv < 32; ++piv) {
                float pinv = 1.0f / aug[piv * 97 + piv];
                float f = rr[piv] * pinv;
                __syncwarp();
                if (r != piv) {
                    const float* pr = &aug[piv * 97];
                    #pragma unroll
                    for (int j = jb; j < 97; j += 8)
                        rr[j] -= f * pr[j];
                }
                __syncthreads();
            }
            if (tid < 32) dinv[tid] = 1.0f / aug[tid * 97 + tid];
            if (tid == 0) red[0] = 0;
            __syncthreads();
        }

        // ---- K_t = (D^-1 * aug_right)^T -> global; track max |dK| ----
        {
            float lmax = 0.0f;
            for (int idx = tid; idx < SD * NV; idx += 256) {
                int s = idx >> 5, v = idx & 31;
                float kv = aug[v * 97 + 32 + s] * dinv[v];
                g_K[t * (SD * NV) + idx] = kv;
                lmax = fmaxf(lmax, fabsf(kv - Kb[idx]));
                Kb[idx] = kv;
            }
            #pragma unroll
            for (int off = 16; off; off >>= 1)
                lmax = fmaxf(lmax, __shfl_xor_sync(0xffffffffu, lmax, off));
            if ((tid & 31) == 0) atomicMax(red, __float_as_int(lmax));
        }
        __syncthreads();

        if (t == TT - 2) break;

        // Converged: remaining gains equal to fp32 precision -> fill & exit.
        if (t >= 10 && __int_as_float(red[0]) < 2e-6f) {
            for (int tt = t + 1; tt < TT - 1; ++tt)
                for (int idx = tid; idx < SD * NV; idx += 256)
                    g_K[tt * (SD * NV) + idx] = Kb[idx];
            break;
        }

        // fold D^-1 into PHt so T1 = P - PHt @ aug_right
        for (int idx = tid; idx < 64 * 32; idx += 256) {
            int i = idx >> 5, v = idx & 31;
            PHt[i * 33 + v] *= dinv[v];
        }
        __syncthreads();

        // ---- T1 = P - PHt @ aug_right ----
        {
            int i0 = ty * 4, j0 = tx * 4;
            float acc[4][4];
            #pragma unroll
            for (int r = 0; r < 4; ++r)
                #pragma unroll
                for (int c = 0; c < 4; ++c)
                    acc[r][c] = P[(i0 + r) * 65 + j0 + c];
            #pragma unroll 4
            for (int v = 0; v < 32; ++v) {
                float a0 = PHt[(i0    ) * 33 + v];
                float a1 = PHt[(i0 + 1) * 33 + v];
                float a2 = PHt[(i0 + 2) * 33 + v];
                float a3 = PHt[(i0 + 3) * 33 + v];
                const float* bp = &aug[v * 97 + 32 + j0];
                float b0 = bp[0], b1 = bp[1], b2 = bp[2], b3 = bp[3];
                acc[0][0] -= a0 * b0; acc[0][1] -= a0 * b1; acc[0][2] -= a0 * b2; acc[0][3] -= a0 * b3;
                acc[1][0] -= a1 * b0; acc[1][1] -= a1 * b1; acc[1][2] -= a1 * b2; acc[1][3] -= a1 * b3;
                acc[2][0] -= a2 * b0; acc[2][1] -= a2 * b1; acc[2][2] -= a2 * b2; acc[2][3] -= a2 * b3;
                acc[3][0] -= a3 * b0; acc[3][1] -= a3 * b1; acc[3][2] -= a3 * b2; acc[3][3] -= a3 * b3;
            }
            #pragma unroll
            for (int r = 0; r < 4; ++r)
                #pragma unroll
                for (int c = 0; c < 4; ++c)
                    T1[(i0 + r) * 65 + j0 + c] = acc[r][c];
        }
        __syncthreads();

        // ---- T2 = F @ T1 ----
        {
            int i0 = ty * 4, j0 = tx * 4;
            float acc[4][4] = {};
            #pragma unroll 4
            for (int k = 0; k < 64; ++k) {
                float a0 = sF[(i0    ) * 65 + k];
                float a1 = sF[(i0 + 1) * 65 + k];
                float a2 = sF[(i0 + 2) * 65 + k];
                float a3 = sF[(i0 + 3) * 65 + k];
                const float* bp = &T1[k * 65 + j0];
                float b0 = bp[0], b1 = bp[1], b2 = bp[2], b3 = bp[3];
                acc[0][0] += a0 * b0; acc[0][1] += a0 * b1; acc[0][2] += a0 * b2; acc[0][3] += a0 * b3;
                acc[1][0] += a1 * b0; acc[1][1] += a1 * b1; acc[1][2] += a1 * b2; acc[1][3] += a1 * b3;
                acc[2][0] += a2 * b0; acc[2][1] += a2 * b1; acc[2][2] += a2 * b2; acc[2][3] += a2 * b3;
                acc[3][0] += a3 * b0; acc[3][1] += a3 * b1; acc[3][2] += a3 * b2; acc[3][3] += a3 * b3;
            }
            #pragma unroll
            for (int r = 0; r < 4; ++r)
                #pragma unroll
                for (int c = 0; c < 4; ++c)
                    T2[(i0 + r) * 65 + j0 + c] = acc[r][c];
        }
        __syncthreads();

        // ---- P = T2 @ F^T + Q ----
        {
            int i0 = ty * 4, j0 = tx * 4;
            float acc[4][4];
            #pragma unroll
            for (int r = 0; r < 4; ++r)
                #pragma unroll
                for (int c = 0; c < 4; ++c)
                    acc[r][c] = sQ[(i0 + r) * 65 + j0 + c];
            #pragma unroll 4
            for (int k = 0; k < 64; ++k) {
                float a0 = T2[(i0    ) * 65 + k];
                float a1 = T2[(i0 + 1) * 65 + k];
                float a2 = T2[(i0 + 2) * 65 + k];
                float a3 = T2[(i0 + 3) * 65 + k];
                float b0 = sF[(j0    ) * 65 + k];
                float b1 = sF[(j0 + 1) * 65 + k];
                float b2 = sF[(j0 + 2) * 65 + k];
                float b3 = sF[(j0 + 3) * 65 + k];
                acc[0][0] += a0 * b0; acc[0][1] += a0 * b1; acc[0][2] += a0 * b2; acc[0][3] += a0 * b3;
                acc[1][0] += a1 * b0; acc[1][1] += a1 * b1; acc[1][2] += a1 * b2; acc[1][3] += a1 * b3;
                acc[2][0] += a2 * b0; acc[2][1] += a2 * b1; acc[2][2] += a2 * b2; acc[2][3] += a2 * b3;
                acc[3][0] += a3 * b0; acc[3][1] += a3 * b1; acc[3][2] += a3 * b2; acc[3][3] += a3 * b3;
            }
            #pragma unroll
            for (int r = 0; r < 4; ++r)
                #pragma unroll
                for (int c = 0; c < 4; ++c)
                    P[(i0 + r) * 65 + j0 + c] = acc[r][c];
        }
        __syncthreads();
    }
}

// ---------------------------------------------------------------------------
// Phase 2: one CTA per batch. y_{t+1} = H m_{t+1} is carried as next step's
// innovation term (computed once). 4-way split accumulators break the
// latency-bound serial FMA chains.
// ---------------------------------------------------------------------------
__global__ __launch_bounds__(64, 1) void kf_phase2(
    const float* __restrict__ x, const float* __restrict__ Fm,
    const float* __restrict__ Hm, float* __restrict__ out)
{
    __shared__ float sH[32 * 65];
    __shared__ float sF[64 * 65];
    __shared__ float sx[32 * 128];
    __shared__ float m[64];
    __shared__ float mu[64];
    __shared__ float resid[32];
    __shared__ float hm[32];

    const int b = blockIdx.x;
    const int tid = threadIdx.x;

    for (int idx = tid; idx < 64 * 64; idx += 64) {
        int i = idx >> 6, j = idx & 63;
        sF[i * 65 + j] = Fm[idx];
    }
    for (int idx = tid; idx < 32 * 64; idx += 64) {
        int i = idx >> 6, j = idx & 63;
        sH[i * 65 + j] = Hm[idx];
    }
    for (int idx = tid; idx < 32 * 128; idx += 64)
        sx[idx] = x[b * (32 * 128) + idx];
    m[tid] = 0.0f;
    if (tid < 32) {
        hm[tid] = 0.0f;                              // H @ 0
        out[b * (32 * 128) + tid * 128 + 0] = 0.0f;  // t = 0 column
    }
    __syncthreads();

    const float4* Kp = reinterpret_cast<const float4*>(g_K);
    float4 kreg[8];
    #pragma unroll
    for (int q = 0; q < 8; ++q) kreg[q] = Kp[(0 * 64 + tid) * 8 + q];

    for (int t = 0; t < TT - 1; ++t) {
        // resid = o_t - (H @ m) [carried in hm]
        if (tid < 32) resid[tid] = sx[tid * 128 + t] - hm[tid];
        __syncthreads();

        // mu = m + K_t @ resid (K row in registers); prefetch next K row
        {
            float a0 = m[tid], a1 = 0, a2 = 0, a3 = 0;
            #pragma unroll
            for (int q = 0; q < 8; q += 4) {
                float4 k0 = kreg[q], k1 = kreg[q+1], k2 = kreg[q+2], k3 = kreg[q+3];
                a0 += k0.x * resid[(q  )*4+0] + k0.y * resid[(q  )*4+1]
                    + k0.z * resid[(q  )*4+2] + k0.w * resid[(q  )*4+3];
                a1 += k1.x * resid[(q+1)*4+0] + k1.y * resid[(q+1)*4+1]
                    + k1.z * resid[(q+1)*4+2] + k1.w * resid[(q+1)*4+3];
                a2 += k2.x * resid[(q+2)*4+0] + k2.y * resid[(q+2)*4+1]
                    + k2.z * resid[(q+2)*4+2] + k2.w * resid[(q+2)*4+3];
                a3 += k3.x * resid[(q+3)*4+0] + k3.y * resid[(q+3)*4+1]
                    + k3.z * resid[(q+3)*4+2] + k3.w * resid[(q+3)*4+3];
            }
            mu[tid] = (a0 + a1) + (a2 + a3);
            if (t + 1 < TT - 1) {
                #pragma unroll
                for (int q = 0; q < 8; ++q)
                    kreg[q] = Kp[((t + 1) * 64 + tid) * 8 + q];
            }
        }
        __syncthreads();

        // m = F @ mu  (4 split accumulators)
        {
            const float* fr = &sF[tid * 65];
            float a0 = 0, a1 = 0, a2 = 0, a3 = 0;
            #pragma unroll
            for (int k = 0; k < 64; k += 4) {
                a0 += fr[k    ] * mu[k    ];
                a1 += fr[k + 1] * mu[k + 1];
                a2 += fr[k + 2] * mu[k + 2];
                a3 += fr[k + 3] * mu[k + 3];
            }
            m[tid] = (a0 + a1) + (a2 + a3);
        }
        __syncthreads();

        // hm = H @ m ; also the output column t+1
        if (tid < 32) {
            const float* hr = &sH[tid * 65];
            float a0 = 0, a1 = 0, a2 = 0, a3 = 0;
            #pragma unroll
            for (int k = 0; k < 64; k += 4) {
                a0 += hr[k    ] * m[k    ];
                a1 += hr[k + 1] * m[k + 1];
                a2 += hr[k + 2] * m[k + 2];
                a3 += hr[k + 3] * m[k + 3];
            }
            float y = (a0 + a1) + (a2 + a3);
            hm[tid] = y;
            out[b * (32 * 128) + tid * 128 + (t + 1)] = y;
        }
        __syncthreads();
    }
}

extern "C" void kernel_launch(void* const* d_in, const int* in_sizes, int n_in,
                              void* d_out, int out_size)
{
    const float* x = (const float*)d_in[0];
    const float* F = (const float*)d_in[1];
    const float* H = (const float*)d_in[2];
    const float* R = (const float*)d_in[3];
    const float* Q = (const float*)d_in[4];
    float* out = (float*)d_out;

    const int smem1 = (64 * 65 * 5 + 32 * 65 + 32 * 33 + 64 * 33 + 32 * 97
                       + 32 + 64 * 32 + 4) * (int)sizeof(float);
    cudaFuncSetAttribute(kf_phase1, cudaFuncAttributeMaxDynamicSharedMemorySize, smem1);

    kf_phase1<<<1, 256, smem1>>>(F, H, R, Q);
    kf_phase2<<<BSZ, 64>>>(x, F, H, out);
}

// round 4
// speedup vs baseline: 14.4683x; 1.9391x over previous
#include <cuda_runtime.h>
#include <math.h>

#define TT 128
#define BSZ 128
#define NV 32
#define SD 64

// Gain matrices K_t (only t <= g_tc valid), layout K[t][(s)*32 + v]
__device__ float g_K[(TT - 1) * SD * NV];
// Combined step operators G_t = [[A,B],[HA,HB]], stored as float4-chunk-major:
// element (row r, col c) of G_t at g_G[t*9216 + (c>>2)*384 + r*4 + (c&3)]
__device__ float g_G[(TT - 1) * 96 * 96];
// Convergence step (last distinct t)
__device__ int g_tc;

// ---------------------------------------------------------------------------
// Phase 1: single CTA, 256 threads. Batch-independent Riccati / gain chain.
// Rank-2 Gauss-Jordan (16 barriers), symmetric-tile P updates, early exit.
// ---------------------------------------------------------------------------
__global__ __launch_bounds__(256, 1) void kf_phase1(
    const float* __restrict__ Fm, const float* __restrict__ Hm,
    const float* __restrict__ Rm, const float* __restrict__ Qm)
{
    extern __shared__ float sm[];
    float* sF   = sm;                 // [64][65]
    float* sH   = sF  + 64 * 65;      // [32][65]
    float* sR   = sH  + 32 * 65;      // [32][33]
    float* sQ   = sR  + 32 * 33;      // [64][65]
    float* P    = sQ  + 64 * 65;      // [64][65]
    float* T1   = P   + 64 * 65;      // [64][65]
    float* T2   = T1  + 64 * 65;      // [64][65]
    float* PHt  = T2  + 64 * 65;      // [64][33]
    float* aug  = PHt + 64 * 33;      // [32][97]  (S | PHt^T)
    float* Kb   = aug + 32 * 97;      // [64*32] previous K (convergence)
    int*   red  = (int*)(Kb + 64 * 32); // [1]

    const int tid = threadIdx.x;
    if (tid == 0) g_tc = TT - 2;      // default: no convergence

    // Lower-triangle 4x4-tile mapping for tid < 136
    int tri_i = 0, tri_j = 0;
    {
        int q = (tid < 136) ? tid : 0;
        tri_i = (int)((sqrtf(8.0f * (float)q + 1.0f) - 1.0f) * 0.5f);
        while ((tri_i + 1) * (tri_i + 2) / 2 <= q) ++tri_i;
        while (tri_i * (tri_i + 1) / 2 > q) --tri_i;
        tri_j = q - tri_i * (tri_i + 1) / 2;
    }

    for (int idx = tid; idx < 64 * 64; idx += 256) {
        int i = idx >> 6, j = idx & 63;
        sF[i * 65 + j] = Fm[idx];
        sQ[i * 65 + j] = Qm[idx];
        P [i * 65 + j] = (i == j) ? 1.0f : 0.0f;
    }
    for (int idx = tid; idx < 32 * 64; idx += 256) {
        int i = idx >> 6, j = idx & 63;
        sH[i * 65 + j] = Hm[idx];
    }
    for (int idx = tid; idx < 32 * 32; idx += 256) {
        int i = idx >> 5, j = idx & 31;
        sR[i * 33 + j] = Rm[idx];
    }
    for (int idx = tid; idx < 64 * 32; idx += 256) Kb[idx] = 1e30f;
    __syncthreads();

    const int ty = tid >> 4;   // 0..15
    const int tx = tid & 15;   // 0..15

    for (int t = 0; t < TT - 1; ++t) {
        // ---- PHt[64][32] = P @ H^T ----
        {
            int i0 = ty * 4, v0 = tx * 2;
            float a00 = 0, a01 = 0, a10 = 0, a11 = 0;
            float a20 = 0, a21 = 0, a30 = 0, a31 = 0;
            #pragma unroll 8
            for (int k = 0; k < 64; ++k) {
                float b0 = sH[(v0    ) * 65 + k];
                float b1 = sH[(v0 + 1) * 65 + k];
                float p0 = P[(i0    ) * 65 + k];
                float p1 = P[(i0 + 1) * 65 + k];
                float p2 = P[(i0 + 2) * 65 + k];
                float p3 = P[(i0 + 3) * 65 + k];
                a00 += p0 * b0; a01 += p0 * b1;
                a10 += p1 * b0; a11 += p1 * b1;
                a20 += p2 * b0; a21 += p2 * b1;
                a30 += p3 * b0; a31 += p3 * b1;
            }
            PHt[(i0    ) * 33 + v0] = a00; PHt[(i0    ) * 33 + v0 + 1] = a01;
            PHt[(i0 + 1) * 33 + v0] = a10; PHt[(i0 + 1) * 33 + v0 + 1] = a11;
            PHt[(i0 + 2) * 33 + v0] = a20; PHt[(i0 + 2) * 33 + v0 + 1] = a21;
            PHt[(i0 + 3) * 33 + v0] = a30; PHt[(i0 + 3) * 33 + v0 + 1] = a31;
        }
        __syncthreads();

        // ---- aug left = S = H @ PHt + R ; aug right = PHt^T ----
        {
            int i  = tid >> 3;
            int j0 = (tid & 7) * 4;
            float c0 = 0, c1 = 0, c2 = 0, c3 = 0;
            #pragma unroll 8
            for (int k = 0; k < 64; ++k) {
                float a = sH[i * 65 + k];
                const float* bp = &PHt[k * 33 + j0];
                c0 += a * bp[0]; c1 += a * bp[1];
                c2 += a * bp[2]; c3 += a * bp[3];
            }
            aug[i * 97 + j0    ] = c0 + sR[i * 33 + j0    ];
            aug[i * 97 + j0 + 1] = c1 + sR[i * 33 + j0 + 1];
            aug[i * 97 + j0 + 2] = c2 + sR[i * 33 + j0 + 2];
            aug[i * 97 + j0 + 3] = c3 + sR[i * 33 + j0 + 3];
        }
        for (int idx = tid; idx < 32 * 64; idx += 256) {
            int i = idx >> 6, j = idx & 63;
            aug[i * 97 + 32 + j] = PHt[j * 33 + i];
        }
        __syncthreads();

        // ---- Rank-2 Gauss-Jordan: 16 barriers. Left part -> 2x2 block diag.
        {
            const int r  = tid >> 3;
            const int jb = tid & 7;
            float* rr = &aug[r * 97];
            for (int piv = 0; piv < 32; piv += 2) {
                const float* pr0 = &aug[piv * 97];
                const float* pr1 = pr0 + 97;
                float a  = pr0[piv], b2 = pr0[piv + 1];
                float c  = pr1[piv], d  = pr1[piv + 1];
                float idet = 1.0f / (a * d - b2 * c);
                float u = rr[piv], v = rr[piv + 1];
                float f0 = (u * d - v * c) * idet;
                float f1 = (v * a - u * b2) * idet;
                __syncwarp();
                if (r != piv && r != piv + 1) {
                    #pragma unroll
                    for (int j = jb; j < 97; j += 8)
                        rr[j] -= f0 * pr0[j] + f1 * pr1[j];
                }
                __syncthreads();
            }
        }
        // ---- In-place 2x2 block solve of right half: aug_right := S^-1 PHt^T
        {
            int pair = tid >> 4;            // 0..15
            int jg   = (tid & 15) * 4;      // 0..60
            int p0 = pair * 2, p1 = p0 + 1;
            float a  = aug[p0 * 97 + p0], b2 = aug[p0 * 97 + p1];
            float c  = aug[p1 * 97 + p0], d  = aug[p1 * 97 + p1];
            float idet = 1.0f / (a * d - b2 * c);
            #pragma unroll
            for (int jj = 0; jj < 4; ++jj) {
                int j = 32 + jg + jj;
                float r0 = aug[p0 * 97 + j], r1 = aug[p1 * 97 + j];
                aug[p0 * 97 + j] = (d * r0 - b2 * r1) * idet;
                aug[p1 * 97 + j] = (a * r1 - c * r0) * idet;
            }
        }
        if (tid == 0) red[0] = 0;
        __syncthreads();

        // ---- K_t = X^T -> global; track max |dK| ----
        {
            float lmax = 0.0f;
            for (int idx = tid; idx < SD * NV; idx += 256) {
                int s = idx >> 5, v = idx & 31;
                float kv = aug[v * 97 + 32 + s];
                g_K[t * (SD * NV) + idx] = kv;
                lmax = fmaxf(lmax, fabsf(kv - Kb[idx]));
                Kb[idx] = kv;
            }
            #pragma unroll
            for (int off = 16; off; off >>= 1)
                lmax = fmaxf(lmax, __shfl_xor_sync(0xffffffffu, lmax, off));
            if ((tid & 31) == 0) atomicMax(red, __float_as_int(lmax));
        }
        __syncthreads();

        if (t == TT - 2) break;

        // Converged: all later K_t equal (to fp noise) -> record tc, exit.
        if (t >= 6 && __int_as_float(red[0]) < 4e-5f) {
            if (tid == 0) g_tc = t;
            break;
        }

        // ---- T1 = P - PHt @ X   (symmetric: lower tiles + mirror) ----
        if (tid < 136) {
            int i0 = tri_i * 4, j0 = tri_j * 4;
            float acc[4][4];
            #pragma unroll
            for (int r = 0; r < 4; ++r)
                #pragma unroll
                for (int c = 0; c < 4; ++c)
                    acc[r][c] = P[(i0 + r) * 65 + j0 + c];
            #pragma unroll 4
            for (int v = 0; v < 32; ++v) {
                float a0 = PHt[(i0    ) * 33 + v];
                float a1 = PHt[(i0 + 1) * 33 + v];
                float a2 = PHt[(i0 + 2) * 33 + v];
                float a3 = PHt[(i0 + 3) * 33 + v];
                const float* bp = &aug[v * 97 + 32 + j0];
                float b0 = bp[0], b1 = bp[1], b2 = bp[2], b3 = bp[3];
                acc[0][0] -= a0 * b0; acc[0][1] -= a0 * b1; acc[0][2] -= a0 * b2; acc[0][3] -= a0 * b3;
                acc[1][0] -= a1 * b0; acc[1][1] -= a1 * b1; acc[1][2] -= a1 * b2; acc[1][3] -= a1 * b3;
                acc[2][0] -= a2 * b0; acc[2][1] -= a2 * b1; acc[2][2] -= a2 * b2; acc[2][3] -= a2 * b3;
                acc[3][0] -= a3 * b0; acc[3][1] -= a3 * b1; acc[3][2] -= a3 * b2; acc[3][3] -= a3 * b3;
            }
            #pragma unroll
            for (int r = 0; r < 4; ++r)
                #pragma unroll
                for (int c = 0; c < 4; ++c) {
                    T1[(i0 + r) * 65 + j0 + c] = acc[r][c];
                    T1[(j0 + c) * 65 + i0 + r] = acc[r][c];
                }
        }
        __syncthreads();

        // ---- T2 = F @ T1 (full) ----
        {
            int i0 = ty * 4, j0 = tx * 4;
            float acc[4][4] = {};
            #pragma unroll 4
            for (int k = 0; k < 64; ++k) {
                float a0 = sF[(i0    ) * 65 + k];
                float a1 = sF[(i0 + 1) * 65 + k];
                float a2 = sF[(i0 + 2) * 65 + k];
                float a3 = sF[(i0 + 3) * 65 + k];
                const float* bp = &T1[k * 65 + j0];
                float b0 = bp[0], b1 = bp[1], b2 = bp[2], b3 = bp[3];
                acc[0][0] += a0 * b0; acc[0][1] += a0 * b1; acc[0][2] += a0 * b2; acc[0][3] += a0 * b3;
                acc[1][0] += a1 * b0; acc[1][1] += a1 * b1; acc[1][2] += a1 * b2; acc[1][3] += a1 * b3;
                acc[2][0] += a2 * b0; acc[2][1] += a2 * b1; acc[2][2] += a2 * b2; acc[2][3] += a2 * b3;
                acc[3][0] += a3 * b0; acc[3][1] += a3 * b1; acc[3][2] += a3 * b2; acc[3][3] += a3 * b3;
            }
            #pragma unroll
            for (int r = 0; r < 4; ++r)
                #pragma unroll
                for (int c = 0; c < 4; ++c)
                    T2[(i0 + r) * 65 + j0 + c] = acc[r][c];
        }
        __syncthreads();

        // ---- P = T2 @ F^T + Q (symmetric: lower tiles + mirror) ----
        if (tid < 136) {
            int i0 = tri_i * 4, j0 = tri_j * 4;
            float acc[4][4];
            #pragma unroll
            for (int r = 0; r < 4; ++r)
                #pragma unroll
                for (int c = 0; c < 4; ++c)
                    acc[r][c] = sQ[(i0 + r) * 65 + j0 + c];
            #pragma unroll 4
            for (int k = 0; k < 64; ++k) {
                float a0 = T2[(i0    ) * 65 + k];
                float a1 = T2[(i0 + 1) * 65 + k];
                float a2 = T2[(i0 + 2) * 65 + k];
                float a3 = T2[(i0 + 3) * 65 + k];
                float b0 = sF[(j0    ) * 65 + k];
                float b1 = sF[(j0 + 1) * 65 + k];
                float b2 = sF[(j0 + 2) * 65 + k];
                float b3 = sF[(j0 + 3) * 65 + k];
                acc[0][0] += a0 * b0; acc[0][1] += a0 * b1; acc[0][2] += a0 * b2; acc[0][3] += a0 * b3;
                acc[1][0] += a1 * b0; acc[1][1] += a1 * b1; acc[1][2] += a1 * b2; acc[1][3] += a1 * b3;
                acc[2][0] += a2 * b0; acc[2][1] += a2 * b1; acc[2][2] += a2 * b2; acc[2][3] += a2 * b3;
                acc[3][0] += a3 * b0; acc[3][1] += a3 * b1; acc[3][2] += a3 * b2; acc[3][3] += a3 * b3;
            }
            #pragma unroll
            for (int r = 0; r < 4; ++r)
                #pragma unroll
                for (int c = 0; c < 4; ++c) {
                    P[(i0 + r) * 65 + j0 + c] = acc[r][c];
                    P[(j0 + c) * 65 + i0 + r] = acc[r][c];
                }
        }
        __syncthreads();
    }
}

// ---------------------------------------------------------------------------
// Build G_t = [[A,B],[HA,HB]] for t <= tc, one CTA per t.
// A = F - (FK)H, B = FK, [HA|HB] = H @ [A|B].
// ---------------------------------------------------------------------------
__global__ __launch_bounds__(256, 1) void kf_buildG(
    const float* __restrict__ Fm, const float* __restrict__ Hm)
{
    const int t = blockIdx.x;
    if (t > g_tc) return;
    extern __shared__ float sm[];
    float* sF  = sm;               // [64][65]
    float* sH  = sF  + 64 * 65;    // [32][65]
    float* sK  = sH  + 32 * 65;    // [64][33]
    float* sFK = sK  + 64 * 33;    // [64][33]
    float* sAB = sFK + 64 * 33;    // [64][97]
    const int tid = threadIdx.x;

    for (int idx = tid; idx < 64 * 64; idx += 256) {
        int i = idx >> 6, j = idx & 63;
        sF[i * 65 + j] = Fm[idx];
    }
    for (int idx = tid; idx < 32 * 64; idx += 256) {
        int i = idx >> 6, j = idx & 63;
        sH[i * 65 + j] = Hm[idx];
    }
    for (int idx = tid; idx < 64 * 32; idx += 256) {
        int s = idx >> 5, v = idx & 31;
        sK[s * 33 + v] = g_K[t * (SD * NV) + idx];
    }
    __syncthreads();

    // FK = F @ K  [64][32]
    for (int idx = tid; idx < 64 * 32; idx += 256) {
        int r = idx >> 5, v = idx & 31;
        float a0 = 0, a1 = 0, a2 = 0, a3 = 0;
        #pragma unroll
        for (int s = 0; s < 64; s += 4) {
            a0 += sF[r * 65 + s    ] * sK[(s    ) * 33 + v];
            a1 += sF[r * 65 + s + 1] * sK[(s + 1) * 33 + v];
            a2 += sF[r * 65 + s + 2] * sK[(s + 2) * 33 + v];
            a3 += sF[r * 65 + s + 3] * sK[(s + 3) * 33 + v];
        }
        sFK[r * 33 + v] = (a0 + a1) + (a2 + a3);
    }
    __syncthreads();

    float* gG = g_G + t * 9216;

    // A part: rows r<64, cols 0..63: A = F - FK @ H
    {
        int r = tid >> 2, c0 = (tid & 3) * 16;
        float fk[32];
        #pragma unroll
        for (int v = 0; v < 32; ++v) fk[v] = sFK[r * 33 + v];
        float acc[16];
        #pragma unroll
        for (int c = 0; c < 16; ++c) acc[c] = sF[r * 65 + c0 + c];
        #pragma unroll 4
        for (int v = 0; v < 32; ++v) {
            float fkv = fk[v];
            #pragma unroll
            for (int c = 0; c < 16; ++c)
                acc[c] -= fkv * sH[v * 65 + c0 + c];
        }
        #pragma unroll
        for (int c = 0; c < 16; ++c) {
            int cc = c0 + c;
            sAB[r * 97 + cc] = acc[c];
            gG[(cc >> 2) * 384 + r * 4 + (cc & 3)] = acc[c];
        }
    }
    // B part: rows r<64, cols 64..95: B = FK
    for (int idx = tid; idx < 64 * 32; idx += 256) {
        int r = idx >> 5, v = idx & 31;
        float val = sFK[r * 33 + v];
        int cc = 64 + v;
        sAB[r * 97 + cc] = val;
        gG[(cc >> 2) * 384 + r * 4 + (cc & 3)] = val;
    }
    __syncthreads();

    // H rows: G(64+w, :) = H(w,:) @ AB
    {
        int w = tid >> 3, c0 = (tid & 7) * 12;
        float acc[12];
        #pragma unroll
        for (int c = 0; c < 12; ++c) acc[c] = 0.0f;
        #pragma unroll 4
        for (int r = 0; r < 64; ++r) {
            float hw = sH[w * 65 + r];
            #pragma unroll
            for (int c = 0; c < 12; ++c)
                acc[c] += hw * sAB[r * 97 + c0 + c];
        }
        #pragma unroll
        for (int c = 0; c < 12; ++c) {
            int cc = c0 + c;
            gG[(cc >> 2) * 384 + (64 + w) * 4 + (cc & 3)] = acc[c];
        }
    }
}

// ---------------------------------------------------------------------------
// Phase 2: one CTA (96 threads) per batch. Single dependent stage per step:
// [m_{t+1}; y_{t+1}] = G_t [m_t; o_t].  G row in registers (reused after tc),
// z double-buffered in smem, ONE barrier per step.
// ---------------------------------------------------------------------------
__global__ __launch_bounds__(96, 1) void kf_phase2(
    const float* __restrict__ x, float* __restrict__ out)
{
    __shared__ float sx[32 * 129];
    __shared__ float sy[32 * 129];
    __shared__ __align__(16) float z[2][96];

    const int b = blockIdx.x;
    const int tid = threadIdx.x;

    for (int idx = tid; idx < 32 * 128; idx += 96) {
        int v = idx >> 7, tt = idx & 127;
        sx[v * 129 + tt] = x[b * (32 * 128) + idx];
    }
    if (tid < 64) z[0][tid] = 0.0f;
    if (tid < 32) sy[tid * 129 + 0] = 0.0f;
    __syncthreads();
    if (tid >= 64) z[0][tid] = sx[(tid - 64) * 129 + 0];

    const int tc = g_tc;
    const float4* G4 = reinterpret_cast<const float4*>(g_G);
    float4 grow[24];
    #pragma unroll
    for (int q = 0; q < 24; ++q) grow[q] = G4[q * 96 + tid];   // G_0 row
    __syncthreads();

    for (int t = 0; t < TT - 1; ++t) {
        const float4* zc4 = reinterpret_cast<const float4*>(z[t & 1]);
        float a0 = 0, a1 = 0, a2 = 0, a3 = 0;
        #pragma unroll
        for (int q = 0; q < 24; q += 4) {
            float4 g0 = grow[q], g1 = grow[q + 1], g2 = grow[q + 2], g3 = grow[q + 3];
            float4 z0 = zc4[q], z1 = zc4[q + 1], z2 = zc4[q + 2], z3 = zc4[q + 3];
            a0 += g0.x * z0.x + g0.y * z0.y + g0.z * z0.z + g0.w * z0.w;
            a1 += g1.x * z1.x + g1.y * z1.y + g1.z * z1.z + g1.w * z1.w;
            a2 += g2.x * z2.x + g2.y * z2.y + g2.z * z2.z + g2.w * z2.w;
            a3 += g3.x * z3.x + g3.y * z3.y + g3.z * z3.z + g3.w * z3.w;
        }
        float acc = (a0 + a1) + (a2 + a3);

        // prefetch next distinct G row; after tc, keep converged row in regs
        if (t + 1 <= tc) {
            const float4* Gp = G4 + (t + 1) * (24 * 96);
            #pragma unroll
            for (int q = 0; q < 24; ++q) grow[q] = Gp[q * 96 + tid];
        }

        float* zn = z[(t + 1) & 1];
        if (tid < 64) {
            zn[tid] = acc;                     // m_{t+1}
        } else {
            int v = tid - 64;
            sy[v * 129 + (t + 1)] = acc;       // y_{t+1}
            zn[tid] = (t < TT - 2) ? sx[v * 129 + (t + 1)] : 0.0f;  // o_{t+1}
        }
        __syncthreads();
    }

    for (int idx = tid; idx < 32 * 128; idx += 96) {
        int v = idx >> 7, tt = idx & 127;
        out[b * (32 * 128) + idx] = sy[v * 129 + tt];
    }
}

extern "C" void kernel_launch(void* const* d_in, const int* in_sizes, int n_in,
                              void* d_out, int out_size)
{
    const float* x = (const float*)d_in[0];
    const float* F = (const float*)d_in[1];
    const float* H = (const float*)d_in[2];
    const float* R = (const float*)d_in[3];
    const float* Q = (const float*)d_in[4];
    float* out = (float*)d_out;

    const int smem1 = (64 * 65 * 5 + 32 * 65 + 32 * 33 + 64 * 33 + 32 * 97
                       + 64 * 32 + 4) * (int)sizeof(float);
    const int smem2 = (64 * 65 + 32 * 65 + 64 * 33 * 2 + 64 * 97)
                      * (int)sizeof(float);
    cudaFuncSetAttribute(kf_phase1, cudaFuncAttributeMaxDynamicSharedMemorySize, smem1);
    cudaFuncSetAttribute(kf_buildG, cudaFuncAttributeMaxDynamicSharedMemorySize, smem2);

    kf_phase1<<<1, 256, smem1>>>(F, H, R, Q);
    kf_buildG<<<TT - 1, 256, smem2>>>(F, H);
    kf_phase2<<<BSZ, 96>>>(x, out);
}